// round 7
// baseline (speedup 1.0000x reference)
#include <cuda_runtime.h>

#define Bq 8
#define Nn 1024
#define Mw 64
#define Ee 63456
#define NROWS (Bq*Nn)          /* 8192 node rows */

#define GRID    152
#define NSTREAM (GRID*2)       /* 304 task streams */

typedef unsigned long long ull;

// ---------------- device scratch ----------------
__device__ float g_We[128*64];          // fused We1@We2
__device__ float g_Wn[192*64];          // fused Wn1@Wn2
__device__ float g_be[64];
__device__ float g_bn[64];
__device__ float g_Wcat[64*192];        // edge-side:  [We_edge | Wn_edge | W_e_edge]
__device__ float g_WcatP[64*192];       // node-side:  [We_src  | Wn_src  | Wn_dst ]
__device__ float g_P[NROWS*192];        // node projections [Pes | Pns | Pnd]
__device__ float g_agg[NROWS*64];       // agg_n

__device__ __forceinline__ int node_w(int i)      { return i < Mw ? i : Mw; }
__device__ __forceinline__ int node_start(int i)  { return i <= Mw ? (i*(i-1))/2 : 2016 + (i-Mw)*Mw; }

// ---------------- packed fp32x2 helpers ----------------
__device__ __forceinline__ void fma2(ull &d, ull a, ull b) {
    asm("fma.rn.f32x2 %0, %1, %2, %0;" : "+l"(d) : "l"(a), "l"(b));
}
__device__ __forceinline__ ull fadd2(ull a, ull b) {
    ull d; asm("add.rn.f32x2 %0, %1, %2;" : "=l"(d) : "l"(a), "l"(b)); return d;
}
__device__ __forceinline__ ull bcast2(float x) {
    ull r; asm("mov.b64 %0, {%1, %1};" : "=l"(r) : "f"(x)); return r;
}
__device__ __forceinline__ float2 unpk(ull v) {
    float2 r; asm("mov.b64 {%0, %1}, %2;" : "=f"(r.x), "=f"(r.y) : "l"(v)); return r;
}
__device__ __forceinline__ ull pk(float x, float y) {
    ull r; asm("mov.b64 %0, {%1, %2};" : "=l"(r) : "f"(x), "f"(y)); return r;
}
__device__ __forceinline__ void gbar(int id) {
    asm volatile("bar.sync %0, %1;" :: "r"(id), "r"(256) : "memory");
}

// ---------------- shared layout (floats) for k_fusededge ----------------
#define SZ_AT    (64*66)       /* 4224 */
#define OFF_W1   0             /* 12288 */
#define OFF_W2   12288         /* 4096  */
#define OFF_BE   16384
#define OFF_BN   16448
#define OFF_BO   16512
#define OFF_RCP  16576
#define OFF_AT   16640         /* [2 grp][2 buf][4224] = 16896 */
#define OFF_PET  33536         /* [2][4224] = 8448 */
#define OFF_Q3   41984         /* [2 grp][8][256] ull = 8192 floats */
#define SMEM_FLOATS 50176
#define SMEM_BYTES  (SMEM_FLOATS*4)

// ---------------- K0: fuse the two (linear∘linear) MLPs ----------------
__global__ void k_fuse(const float* __restrict__ We1, const float* __restrict__ We2,
                       const float* __restrict__ be1, const float* __restrict__ be2,
                       const float* __restrict__ Wn1, const float* __restrict__ bn1,
                       const float* __restrict__ Wn2, const float* __restrict__ bn2) {
    int idx = blockIdx.x*blockDim.x + threadIdx.x;
    if (idx < 128*64) {
        int j = idx >> 6, c = idx & 63; float s = 0.f;
        for (int t = 0; t < 128; t++) s += We1[j*128+t]*We2[t*64+c];
        g_We[idx] = s;
    }
    int i2 = idx - 128*64;
    if (i2 >= 0 && i2 < 192*64) {
        int j = i2 >> 6, c = i2 & 63; float s = 0.f;
        for (int t = 0; t < 128; t++) s += Wn1[j*128+t]*Wn2[t*64+c];
        g_Wn[i2] = s;
    }
    int i3 = idx - 128*64 - 192*64;
    if (i3 >= 0 && i3 < 64) {
        float s = be2[i3];
        for (int t = 0; t < 128; t++) s += be1[t]*We2[t*64+i3];
        g_be[i3] = s;
    }
    if (i3 >= 64 && i3 < 128) {
        int c = i3 - 64; float s = bn2[c];
        for (int t = 0; t < 128; t++) s += bn1[t]*Wn2[t*64+c];
        g_bn[c] = s;
    }
}

// ---------------- K0b: pack concatenated weight blocks ----------------
__global__ void k_cat(const float* __restrict__ W_edges) {
    int idx = blockIdx.x*blockDim.x + threadIdx.x;
    if (idx >= 64*192) return;
    int j = idx / 192, c = idx % 192;
    float ve, vp;
    if (c < 64)       { ve = g_We[(64+j)*64 + c];          vp = g_We[j*64 + c]; }
    else if (c < 128) { ve = g_Wn[(128+j)*64 + (c-64)];    vp = g_Wn[j*64 + (c-64)]; }
    else              { ve = W_edges[(64+j)*64 + (c-128)]; vp = g_Wn[(64+j)*64 + (c-128)]; }
    g_Wcat[idx]  = ve;
    g_WcatP[idx] = vp;
}

// ---------------- K1: node projections GEMM (NROWS x 64) @ (64 x 192) ----------------
__global__ void __launch_bounds__(256,2) k_nodeproj(const float* __restrict__ A) {
    __shared__ float sW[64*192];
    __shared__ float sA[64][68];
    for (int idx = threadIdx.x; idx < 64*192; idx += 256) sW[idx] = g_WcatP[idx];
    int tx = threadIdx.x & 31, ty = threadIdx.x >> 5;
    const int NT = NROWS/64;
    for (int tile = blockIdx.x; tile < NT; tile += gridDim.x) {
        __syncthreads();
        const float4* src = (const float4*)(A + (size_t)tile*64*64);
        for (int idx = threadIdx.x; idx < 64*16; idx += 256) {
            int r = idx >> 4, q = idx & 15;
            ((float4*)&sA[r][0])[q] = src[idx];
        }
        __syncthreads();
        float acc[8][6];
        #pragma unroll
        for (int a = 0; a < 8; a++)
            #pragma unroll
            for (int b = 0; b < 6; b++) acc[a][b] = 0.f;
        for (int j = 0; j < 64; j += 4) {
            float4 av[8];
            #pragma unroll
            for (int ri = 0; ri < 8; ri++) av[ri] = *(const float4*)&sA[ty + 8*ri][j];
            #pragma unroll
            for (int jj = 0; jj < 4; jj++) {
                float wv[6];
                #pragma unroll
                for (int ci = 0; ci < 6; ci++) wv[ci] = sW[(j+jj)*192 + tx + 32*ci];
                #pragma unroll
                for (int ri = 0; ri < 8; ri++) {
                    float a = (jj==0) ? av[ri].x : (jj==1) ? av[ri].y : (jj==2) ? av[ri].z : av[ri].w;
                    #pragma unroll
                    for (int ci = 0; ci < 6; ci++) acc[ri][ci] += a * wv[ci];
                }
            }
        }
        float* dst = g_P + (size_t)tile*64*192;
        #pragma unroll
        for (int ri = 0; ri < 8; ri++) {
            int r = ty + 8*ri;
            #pragma unroll
            for (int ci = 0; ci < 6; ci++)
                dst[(size_t)r*192 + tx + 32*ci] = acc[ri][ci];
        }
    }
}

// ---------------- K2: fused per-node pipeline; rows lane-distributed, cols warp-owned ----------------
__global__ void __launch_bounds__(512,1) k_fusededge(const float* __restrict__ edges,
                                                     const float* __restrict__ W_edges,
                                                     const float* __restrict__ bias,
                                                     float* __restrict__ out_edges) {
    extern __shared__ float sm[];
    float* sW1  = sm + OFF_W1;
    float* sW2  = sm + OFF_W2;
    float* sbe  = sm + OFF_BE;
    float* sbn  = sm + OFF_BN;
    float* sbo  = sm + OFF_BO;
    float* srcp = sm + OFF_RCP;
    int tid = threadIdx.x;

    for (int idx = tid; idx < 64*192; idx += 512) sW1[idx] = g_Wcat[idx];
    for (int idx = tid; idx < 64*64;  idx += 512) sW2[idx] = W_edges[idx];
    if (tid < 64) {
        sbe[tid] = g_be[tid];
        sbn[tid] = g_bn[tid];
        sbo[tid] = bias[tid];
        srcp[tid] = 1.0f / (float)(tid > 0 ? tid : 1);
    }
    __syncthreads();

    int grp  = tid >> 8;            // warp-group 0/1
    int gtid = tid & 255;
    int tx = gtid & 31, wg = gtid >> 5;
    int bar = grp + 1;
    int cb = 8*wg;                  // this warp's col base inside each 64-col segment
    int r0 = 2*tx, r1 = 2*tx + 1;   // this thread's rows

    float* sPeT = sm + OFF_PET + grp*SZ_AT;
    float* bufA = sm + OFF_AT + (grp*2+0)*SZ_AT;
    float* bufB = sm + OFF_AT + (grp*2+1)*SZ_AT;
    ull*   sQ3  = (ull*)(sm + OFF_Q3) + grp*2048;

    int task = blockIdx.x*2 + grp;

    // ---- prologue: load first tile into bufA (transposed [j][r]) ----
    {
        int b = task >> 10, i = task & 1023;
        size_t ebase = (size_t)b*Ee + node_start(i);
        const float4* src = (const float4*)(edges + ebase*64);
        #pragma unroll
        for (int k = 0; k < 4; k++) {
            int idx = gtid + 256*k;
            float4 v = __ldg(src + idx);
            int r = idx >> 4, j = 4*(idx & 15);
            bufA[(j+0)*66 + r] = v.x; bufA[(j+1)*66 + r] = v.y;
            bufA[(j+2)*66 + r] = v.z; bufA[(j+3)*66 + r] = v.w;
        }
    }
    gbar(bar);

    float* curAT = bufA;
    float* nxtAT = bufB;

    for (; task < Bq*Nn; task += NSTREAM) {
        int b = task >> 10, i = task & 1023;
        int w = node_w(i), ns = node_start(i);
        size_t ebase = (size_t)b*Ee + ns;
        int srow0 = (b << 10) + (i - w);
        int ntask = task + NSTREAM;
        bool hasn = ntask < Bq*Nn;
        bool v0r = r0 < w, v1r = r1 < w;

        // ---- GEMM1: rows lane-distributed (1 LDS.64), W broadcast (6 LDS.128) ----
        ull acc0[12], acc1[12];
        #pragma unroll
        for (int p = 0; p < 12; p++) { acc0[p] = 0ull; acc1[p] = 0ull; }
        #pragma unroll 8
        for (int j = 0; j < 64; j++) {
            ull a2 = *(const ull*)&curAT[j*66 + r0];
            float2 af = unpk(a2);
            ull aR0 = bcast2(af.x), aR1 = bcast2(af.y);
            #pragma unroll
            for (int s = 0; s < 3; s++) {
                const float* wrow = &sW1[j*192 + 64*s + cb];
                ulonglong2 wA = *(const ulonglong2*)wrow;
                ulonglong2 wB = *(const ulonglong2*)(wrow + 4);
                fma2(acc0[4*s+0], aR0, wA.x); fma2(acc0[4*s+1], aR0, wA.y);
                fma2(acc0[4*s+2], aR0, wB.x); fma2(acc0[4*s+3], aR0, wB.y);
                fma2(acc1[4*s+0], aR1, wA.x); fma2(acc1[4*s+1], aR1, wA.y);
                fma2(acc1[4*s+2], aR1, wB.x); fma2(acc1[4*s+3], aR1, wB.y);
            }
        }

        // ---- stash Q3 to smem (own slots; same-thread RAW needs no barrier) ----
        #pragma unroll
        for (int p = 0; p < 4; p++) {
            sQ3[(2*p+0)*256 + gtid] = acc0[8+p];
            sQ3[(2*p+1)*256 + gtid] = acc1[8+p];
        }

        // ---- epilogue phase 1: pair_e -> sPeT ----
        {
            size_t pr0 = (size_t)(srow0 + r0)*192 + cb;
            size_t pr1 = (size_t)(srow0 + r1)*192 + cb;
            ulonglong2 feA0 = *(const ulonglong2*)&g_P[pr0];
            ulonglong2 feB0 = *(const ulonglong2*)&g_P[pr0 + 4];
            ulonglong2 feA1 = *(const ulonglong2*)&g_P[pr1];
            ulonglong2 feB1 = *(const ulonglong2*)&g_P[pr1 + 4];
            ulonglong2 beA = *(const ulonglong2*)&sbe[cb];
            ulonglong2 beB = *(const ulonglong2*)&sbe[cb + 4];
            ull fe0[4] = {feA0.x, feA0.y, feB0.x, feB0.y};
            ull fe1[4] = {feA1.x, feA1.y, feB1.x, feB1.y};
            ull beu[4] = {beA.x, beA.y, beB.x, beB.y};
            #pragma unroll
            for (int p = 0; p < 4; p++) {
                int c = cb + 2*p;
                ull t0 = fadd2(fadd2(acc0[p], fe0[p]), beu[p]);
                ull t1 = fadd2(fadd2(acc1[p], fe1[p]), beu[p]);
                float2 f0 = unpk(t0), f1 = unpk(t1);
                f0.x = v0r ? fmaxf(f0.x, 0.f) : 0.f;
                f0.y = v0r ? fmaxf(f0.y, 0.f) : 0.f;
                f1.x = v1r ? fmaxf(f1.x, 0.f) : 0.f;
                f1.y = v1r ? fmaxf(f1.y, 0.f) : 0.f;
                *(ull*)&sPeT[(c+0)*66 + r0] = pk(f0.x, f1.x);
                *(ull*)&sPeT[(c+1)*66 + r0] = pk(f0.y, f1.y);
            }
        }

        // ---- epilogue phase 2: pair_n warp sums ----
        ull np[4];
        {
            size_t pr0 = (size_t)(srow0 + r0)*192 + 64 + cb;
            size_t pr1 = (size_t)(srow0 + r1)*192 + 64 + cb;
            ulonglong2 fnA0 = *(const ulonglong2*)&g_P[pr0];
            ulonglong2 fnB0 = *(const ulonglong2*)&g_P[pr0 + 4];
            ulonglong2 fnA1 = *(const ulonglong2*)&g_P[pr1];
            ulonglong2 fnB1 = *(const ulonglong2*)&g_P[pr1 + 4];
            size_t pdb = (size_t)task*192 + 128 + cb;
            ulonglong2 pdA = *(const ulonglong2*)&g_P[pdb];
            ulonglong2 pdB = *(const ulonglong2*)&g_P[pdb + 4];
            ulonglong2 bnA = *(const ulonglong2*)&sbn[cb];
            ulonglong2 bnB = *(const ulonglong2*)&sbn[cb + 4];
            ull fn0[4] = {fnA0.x, fnA0.y, fnB0.x, fnB0.y};
            ull fn1[4] = {fnA1.x, fnA1.y, fnB1.x, fnB1.y};
            ull pdu[4] = {pdA.x, pdA.y, pdB.x, pdB.y};
            ull bnu[4] = {bnA.x, bnA.y, bnB.x, bnB.y};
            #pragma unroll
            for (int p = 0; p < 4; p++) {
                ull u0 = fadd2(fadd2(fadd2(acc0[4+p], fn0[p]), pdu[p]), bnu[p]);
                ull u1 = fadd2(fadd2(fadd2(acc1[4+p], fn1[p]), pdu[p]), bnu[p]);
                float2 g0 = unpk(u0), g1 = unpk(u1);
                float sx = (v0r ? fmaxf(g0.x, 0.f) : 0.f) + (v1r ? fmaxf(g1.x, 0.f) : 0.f);
                float sy = (v0r ? fmaxf(g0.y, 0.f) : 0.f) + (v1r ? fmaxf(g1.y, 0.f) : 0.f);
                np[p] = pk(sx, sy);
            }
        }

        // warp butterfly reduce pair_n sums
        #pragma unroll
        for (int d = 16; d >= 1; d >>= 1) {
            #pragma unroll
            for (int p = 0; p < 4; p++)
                np[p] = fadd2(np[p], __shfl_xor_sync(0xffffffffu, np[p], d));
        }

        // ---- prefetch next tile (LDGs in flight under GEMM2) ----
        float4 pf4[4];
        if (hasn) {
            int nb = ntask >> 10, ni = ntask & 1023;
            size_t nebase = (size_t)nb*Ee + node_start(ni);
            const float4* nsrc = (const float4*)(edges + nebase*64);
            #pragma unroll
            for (int k = 0; k < 4; k++) pf4[k] = __ldg(nsrc + gtid + 256*k);
        }
        gbar(bar);                           // B1: sPeT ready

        // agg_n write (one lane per warp)
        if (tx == 0) {
            float invw = 1.0f / (float)(w > 0 ? w : 1);
            #pragma unroll
            for (int p = 0; p < 4; p++) {
                float2 v = unpk(np[p]);
                float2 o; o.x = v.x*invw; o.y = v.y*invw;
                *(float2*)&g_agg[(size_t)task*64 + cb + 2*p] = o;
            }
        }

        // ---- GEMM2: R = pair_e @ W_mean (8 cols per warp) ----
        ull acc20[4], acc21[4];
        #pragma unroll
        for (int p = 0; p < 4; p++) { acc20[p] = 0ull; acc21[p] = 0ull; }
        #pragma unroll 8
        for (int j = 0; j < 64; j++) {
            ull a2 = *(const ull*)&sPeT[j*66 + r0];
            float2 af = unpk(a2);
            ull aR0 = bcast2(af.x), aR1 = bcast2(af.y);
            const float* wrow = &sW2[j*64 + cb];
            ulonglong2 wA = *(const ulonglong2*)wrow;
            ulonglong2 wB = *(const ulonglong2*)(wrow + 4);
            fma2(acc20[0], aR0, wA.x); fma2(acc20[1], aR0, wA.y);
            fma2(acc20[2], aR0, wB.x); fma2(acc20[3], aR0, wB.y);
            fma2(acc21[0], aR1, wA.x); fma2(acc21[1], aR1, wA.y);
            fma2(acc21[2], aR1, wB.x); fma2(acc21[3], aR1, wB.y);
        }

        // ---- exclusive row-prefix via warp scan (f32x2 over col-pairs) ----
        float ex0x[4], ex0y[4], ex1x[4], ex1y[4];
        #pragma unroll
        for (int p = 0; p < 4; p++) {
            ull loc = fadd2(acc20[p], acc21[p]);
            ull run = loc;
            #pragma unroll
            for (int d = 1; d < 32; d <<= 1) {
                ull t = __shfl_up_sync(0xffffffffu, run, d);
                if (tx >= d) run = fadd2(run, t);
            }
            float2 rr = unpk(run), lc = unpk(loc), v0 = unpk(acc20[p]);
            ex0x[p] = rr.x - lc.x;  ex0y[p] = rr.y - lc.y;
            ex1x[p] = ex0x[p] + v0.x;  ex1y[p] = ex0y[p] + v0.y;
        }

        // ---- store prefetched tile into alternate buffer ----
        if (hasn) {
            #pragma unroll
            for (int k = 0; k < 4; k++) {
                int idx = gtid + 256*k;
                int r = idx >> 4, j = 4*(idx & 15);
                nxtAT[(j+0)*66 + r] = pf4[k].x; nxtAT[(j+1)*66 + r] = pf4[k].y;
                nxtAT[(j+2)*66 + r] = pf4[k].z; nxtAT[(j+3)*66 + r] = pf4[k].w;
            }
        }

        // ---- final: mean-scale + Q3 (from smem) + bias, ReLU, store ----
        float rc0 = srcp[r0], rc1 = srcp[r1];
        #pragma unroll
        for (int p = 0; p < 4; p++) {
            float2 q30 = unpk(sQ3[(2*p+0)*256 + gtid]);
            float2 q31 = unpk(sQ3[(2*p+1)*256 + gtid]);
            float2 bo; bo.x = sbo[cb + 2*p]; bo.y = sbo[cb + 2*p + 1];
            if (v0r) {
                float vx = ex0x[p]*rc0 + q30.x + bo.x;
                float vy = ex0y[p]*rc0 + q30.y + bo.y;
                float2 o; o.x = fmaxf(vx, 0.f); o.y = fmaxf(vy, 0.f);
                *(float2*)&out_edges[(ebase + r0)*64 + cb + 2*p] = o;
            }
            if (v1r) {
                float vx = ex1x[p]*rc1 + q31.x + bo.x;
                float vy = ex1y[p]*rc1 + q31.y + bo.y;
                float2 o; o.x = fmaxf(vx, 0.f); o.y = fmaxf(vy, 0.f);
                *(float2*)&out_edges[(ebase + r1)*64 + cb + 2*p] = o;
            }
        }

        gbar(bar);                           // B2: GEMM2 reads + next tile done
        float* t = curAT; curAT = nxtAT; nxtAT = t;
    }
}

// ---------------- K3: out_nodes (NROWS x 128) @ (128 x 64) ----------------
__global__ void __launch_bounds__(256,2) k_outnodes(float* __restrict__ out,
                                                    const float* __restrict__ nodes,
                                                    const float* __restrict__ W_nodes,
                                                    const float* __restrict__ bias) {
    __shared__ float sW[128*64];
    __shared__ float sA[64][132];
    __shared__ float sb[64];
    for (int idx = threadIdx.x; idx < 128*64; idx += 256) sW[idx] = W_nodes[idx];
    if (threadIdx.x < 64) sb[threadIdx.x] = bias[threadIdx.x];
    int tx = threadIdx.x & 31, ty = threadIdx.x >> 5;
    int tile = blockIdx.x;
    {
        const float4* sa = (const float4*)(g_agg + (size_t)tile*64*64);
        const float4* sn = (const float4*)(nodes + (size_t)tile*64*64);
        for (int idx = threadIdx.x; idx < 64*16; idx += 256) {
            int r = idx >> 4, q = idx & 15;
            ((float4*)&sA[r][0])[q]  = sa[idx];
            ((float4*)&sA[r][64])[q] = sn[idx];
        }
    }
    __syncthreads();
    float acc[8][2];
    #pragma unroll
    for (int a = 0; a < 8; a++) { acc[a][0] = 0.f; acc[a][1] = 0.f; }
    for (int j = 0; j < 128; j += 4) {
        float4 av[8];
        #pragma unroll
        for (int ri = 0; ri < 8; ri++) av[ri] = *(const float4*)&sA[ty + 8*ri][j];
        #pragma unroll
        for (int jj = 0; jj < 4; jj++) {
            float w0 = sW[(j+jj)*64 + tx];
            float w1 = sW[(j+jj)*64 + tx + 32];
            #pragma unroll
            for (int ri = 0; ri < 8; ri++) {
                float a = (jj==0) ? av[ri].x : (jj==1) ? av[ri].y : (jj==2) ? av[ri].z : av[ri].w;
                acc[ri][0] += a * w0;
                acc[ri][1] += a * w1;
            }
        }
    }
    #pragma unroll
    for (int ri = 0; ri < 8; ri++) {
        size_t row = (size_t)tile*64 + ty + 8*ri;
        float v0 = acc[ri][0] + sb[tx];
        float v1 = acc[ri][1] + sb[tx+32];
        out[row*64 + tx]      = v0 > 0.f ? v0 : 0.f;
        out[row*64 + tx + 32] = v1 > 0.f ? v1 : 0.f;
    }
}

// ---------------- launch ----------------
extern "C" void kernel_launch(void* const* d_in, const int* in_sizes, int n_in,
                              void* d_out, int out_size) {
    const float* input_nodes = (const float*)d_in[0];
    const float* input_edges = (const float*)d_in[1];
    const float* Wn1 = (const float*)d_in[2];
    const float* bn1 = (const float*)d_in[3];
    const float* Wn2 = (const float*)d_in[4];
    const float* bn2 = (const float*)d_in[5];
    const float* We1 = (const float*)d_in[6];
    const float* be1 = (const float*)d_in[7];
    const float* We2 = (const float*)d_in[8];
    const float* be2 = (const float*)d_in[9];
    const float* W_nodes    = (const float*)d_in[10];
    const float* W_edges    = (const float*)d_in[11];
    const float* bias_edges = (const float*)d_in[12];

    float* out       = (float*)d_out;
    float* out_nodes = out;
    float* out_edges = out + (size_t)Bq*Nn*64;

    cudaFuncSetAttribute(k_fusededge, cudaFuncAttributeMaxDynamicSharedMemorySize, SMEM_BYTES);

    k_fuse<<<(128*64 + 192*64 + 128 + 255)/256, 256>>>(We1, We2, be1, be2, Wn1, bn1, Wn2, bn2);
    k_cat<<<(64*192 + 255)/256, 256>>>(W_edges);
    k_nodeproj<<<128, 256>>>(input_nodes);
    k_fusededge<<<GRID, 512, SMEM_BYTES>>>(input_edges, W_edges, bias_edges, out_edges);
    k_outnodes<<<128, 256>>>(out_nodes, input_nodes, W_nodes, bias_edges);
}

// round 8
// speedup vs baseline: 1.3124x; 1.3124x over previous
#include <cuda_runtime.h>

#define Bq 8
#define Nn 1024
#define Mw 64
#define Ee 63456
#define NROWS (Bq*Nn)          /* 8192 node rows */
#define NTASK (Bq*Nn)

#define GRID    152
#define NSTREAM (GRID*2)       /* 304 task streams */

typedef unsigned long long ull;

// ---------------- device scratch ----------------
__device__ float g_We[128*64];          // fused We1@We2
__device__ float g_Wn[192*64];          // fused Wn1@Wn2
__device__ float g_be[64];
__device__ float g_bn[64];
__device__ float g_Wcat[64*192];        // edge-side:  [We_edge | Wn_edge | W_e_edge]
__device__ float g_WcatP[64*192];       // node-side:  [We_src  | Wn_src  | Wn_dst ]
__device__ float g_P[NROWS*192];        // node projections [Pes | Pns | Pnd]

__device__ __forceinline__ int node_w(int i)      { return i < Mw ? i : Mw; }
__device__ __forceinline__ int node_start(int i)  { return i <= Mw ? (i*(i-1))/2 : 2016 + (i-Mw)*Mw; }

// ---------------- packed fp32x2 helpers ----------------
__device__ __forceinline__ void fma2(ull &d, ull a, ull b) {
    asm("fma.rn.f32x2 %0, %1, %2, %0;" : "+l"(d) : "l"(a), "l"(b));
}
__device__ __forceinline__ ull fadd2(ull a, ull b) {
    ull d; asm("add.rn.f32x2 %0, %1, %2;" : "=l"(d) : "l"(a), "l"(b)); return d;
}
__device__ __forceinline__ ull bcast2(float x) {
    ull r; asm("mov.b64 %0, {%1, %1};" : "=l"(r) : "f"(x)); return r;
}
__device__ __forceinline__ float2 unpk(ull v) {
    float2 r; asm("mov.b64 {%0, %1}, %2;" : "=f"(r.x), "=f"(r.y) : "l"(v)); return r;
}
__device__ __forceinline__ ull pk(float x, float y) {
    ull r; asm("mov.b64 %0, {%1, %2};" : "=l"(r) : "f"(x), "f"(y)); return r;
}
__device__ __forceinline__ void gbar(int id) {
    asm volatile("bar.sync %0, %1;" :: "r"(id), "r"(256) : "memory");
}
__device__ __forceinline__ void mbar64(int id) {
    asm volatile("bar.sync %0, %1;" :: "r"(id), "r"(64) : "memory");
}

// ---------------- shared layout (floats) for k_fusededge ----------------
#define SZ_AT    (64*66)       /* 4224 */
#define OFF_W1   0             /* 12288 */
#define OFF_W2   12288         /* 4096  */
#define OFF_W3   16384         /* 8192  W_nodes 128x64 */
#define OFF_BE   24576
#define OFF_BN   24640
#define OFF_BO   24704
#define OFF_RCP  24768
#define OFF_AT   24832         /* [2 grp][2 buf][4224] = 16896 */
#define OFF_PET  41728         /* [2 grp][4224] = 8448 */
#define OFF_SRED 50176         /* [2 grp][2 par][512] = 2048 */
#define OFF_SWR  52224         /* [2 grp][2 par][256 ull] = 2048 floats */
#define OFF_SND  54272         /* [2 grp][2 par][64] = 256 */
#define OFF_SAGG 54528         /* [2 grp][64] = 128 */
#define SMEM_FLOATS 54656
#define SMEM_BYTES  (SMEM_FLOATS*4)

// ---------------- K0: fuse the two (linear∘linear) MLPs ----------------
__global__ void k_fuse(const float* __restrict__ We1, const float* __restrict__ We2,
                       const float* __restrict__ be1, const float* __restrict__ be2,
                       const float* __restrict__ Wn1, const float* __restrict__ bn1,
                       const float* __restrict__ Wn2, const float* __restrict__ bn2) {
    int idx = blockIdx.x*blockDim.x + threadIdx.x;
    if (idx < 128*64) {
        int j = idx >> 6, c = idx & 63; float s = 0.f;
        for (int t = 0; t < 128; t++) s += We1[j*128+t]*We2[t*64+c];
        g_We[idx] = s;
    }
    int i2 = idx - 128*64;
    if (i2 >= 0 && i2 < 192*64) {
        int j = i2 >> 6, c = i2 & 63; float s = 0.f;
        for (int t = 0; t < 128; t++) s += Wn1[j*128+t]*Wn2[t*64+c];
        g_Wn[i2] = s;
    }
    int i3 = idx - 128*64 - 192*64;
    if (i3 >= 0 && i3 < 64) {
        float s = be2[i3];
        for (int t = 0; t < 128; t++) s += be1[t]*We2[t*64+i3];
        g_be[i3] = s;
    }
    if (i3 >= 64 && i3 < 128) {
        int c = i3 - 64; float s = bn2[c];
        for (int t = 0; t < 128; t++) s += bn1[t]*Wn2[t*64+c];
        g_bn[c] = s;
    }
}

// ---------------- K0b: pack concatenated weight blocks ----------------
__global__ void k_cat(const float* __restrict__ W_edges) {
    int idx = blockIdx.x*blockDim.x + threadIdx.x;
    if (idx >= 64*192) return;
    int j = idx / 192, c = idx % 192;
    float ve, vp;
    if (c < 64)       { ve = g_We[(64+j)*64 + c];          vp = g_We[j*64 + c]; }
    else if (c < 128) { ve = g_Wn[(128+j)*64 + (c-64)];    vp = g_Wn[j*64 + (c-64)]; }
    else              { ve = W_edges[(64+j)*64 + (c-128)]; vp = g_Wn[(64+j)*64 + (c-128)]; }
    g_Wcat[idx]  = ve;
    g_WcatP[idx] = vp;
}

// ---------------- K1: node projections GEMM (NROWS x 64) @ (64 x 192) ----------------
__global__ void __launch_bounds__(256,2) k_nodeproj(const float* __restrict__ A) {
    __shared__ float sW[64*192];
    __shared__ float sA[64][68];
    for (int idx = threadIdx.x; idx < 64*192; idx += 256) sW[idx] = g_WcatP[idx];
    int tx = threadIdx.x & 31, ty = threadIdx.x >> 5;
    const int NT = NROWS/64;
    for (int tile = blockIdx.x; tile < NT; tile += gridDim.x) {
        __syncthreads();
        const float4* src = (const float4*)(A + (size_t)tile*64*64);
        for (int idx = threadIdx.x; idx < 64*16; idx += 256) {
            int r = idx >> 4, q = idx & 15;
            ((float4*)&sA[r][0])[q] = src[idx];
        }
        __syncthreads();
        float acc[8][6];
        #pragma unroll
        for (int a = 0; a < 8; a++)
            #pragma unroll
            for (int b = 0; b < 6; b++) acc[a][b] = 0.f;
        for (int j = 0; j < 64; j += 4) {
            float4 av[8];
            #pragma unroll
            for (int ri = 0; ri < 8; ri++) av[ri] = *(const float4*)&sA[ty + 8*ri][j];
            #pragma unroll
            for (int jj = 0; jj < 4; jj++) {
                float wv[6];
                #pragma unroll
                for (int ci = 0; ci < 6; ci++) wv[ci] = sW[(j+jj)*192 + tx + 32*ci];
                #pragma unroll
                for (int ri = 0; ri < 8; ri++) {
                    float a = (jj==0) ? av[ri].x : (jj==1) ? av[ri].y : (jj==2) ? av[ri].z : av[ri].w;
                    #pragma unroll
                    for (int ci = 0; ci < 6; ci++) acc[ri][ci] += a * wv[ci];
                }
            }
        }
        float* dst = g_P + (size_t)tile*64*192;
        #pragma unroll
        for (int ri = 0; ri < 8; ri++) {
            int r = ty + 8*ri;
            #pragma unroll
            for (int ci = 0; ci < 6; ci++)
                dst[(size_t)r*192 + tx + 32*ci] = acc[ri][ci];
        }
    }
}

// ---------------- K2: fused pipeline (R5 mapping), 1 barrier/task, fused out_nodes ----------------
__global__ void __launch_bounds__(512,1) k_fusededge(const float* __restrict__ edges,
                                                     const float* __restrict__ nodes,
                                                     const float* __restrict__ W_edges,
                                                     const float* __restrict__ W_nodes,
                                                     const float* __restrict__ bias,
                                                     float* __restrict__ out_edges,
                                                     float* __restrict__ out_nodes) {
    extern __shared__ float sm[];
    float* sW1  = sm + OFF_W1;
    float* sW2  = sm + OFF_W2;
    float* sW3  = sm + OFF_W3;
    float* sbe  = sm + OFF_BE;
    float* sbn  = sm + OFF_BN;
    float* sbo  = sm + OFF_BO;
    float* srcp = sm + OFF_RCP;
    int tid = threadIdx.x;

    for (int idx = tid; idx < 64*192; idx += 512) sW1[idx] = g_Wcat[idx];
    for (int idx = tid; idx < 64*64;  idx += 512) sW2[idx] = W_edges[idx];
    for (int idx = tid; idx < 128*64; idx += 512) sW3[idx] = W_nodes[idx];
    if (tid < 64) {
        sbe[tid] = g_be[tid];
        sbn[tid] = g_bn[tid];
        sbo[tid] = bias[tid];
        srcp[tid] = 1.0f / (float)(tid > 0 ? tid : 1);
    }
    __syncthreads();

    int grp  = tid >> 8;            // warp-group 0/1
    int gtid = tid & 255;
    int tx = gtid & 31, ty = gtid >> 5;
    int bar = grp + 1;
    int mb  = grp + 3;
    int r0t = 8*ty;                 // this warp's first row

    float* sPeT  = sm + OFF_PET  + grp*SZ_AT;
    float* bufA  = sm + OFF_AT + (grp*2+0)*SZ_AT;
    float* bufB  = sm + OFF_AT + (grp*2+1)*SZ_AT;
    float* sredB = sm + OFF_SRED + grp*1024;
    ull*   swrB  = (ull*)(sm + OFF_SWR) + grp*512;
    float* sndB  = sm + OFF_SND + grp*128;
    float* sagg  = sm + OFF_SAGG + grp*64;

    int task = blockIdx.x*2 + grp;

    // ---- prologue: own-warp rows of first tile + first snode ----
    {
        int b = task >> 10, i = task & 1023;
        size_t ebase = (size_t)b*Ee + node_start(i);
        const float4* src = (const float4*)(edges + ebase*64);
        #pragma unroll
        for (int k = 0; k < 4; k++) {
            int idx = tx + 32*k;
            int rl = idx >> 4, q = idx & 15;
            float4 v = __ldg(src + (r0t + rl)*16 + q);
            int j = 4*q, r = r0t + rl;
            bufA[(j+0)*66 + r] = v.x; bufA[(j+1)*66 + r] = v.y;
            bufA[(j+2)*66 + r] = v.z; bufA[(j+3)*66 + r] = v.w;
        }
        if (gtid < 16) {
            float4 v = __ldg((const float4*)(nodes + (size_t)task*64) + gtid);
            *(float4*)&sndB[4*gtid] = v;
        }
    }
    __syncwarp();

    float* curAT = bufA;
    float* nxtAT = bufB;
    int par = 0;

    for (; task < NTASK; task += NSTREAM, par ^= 1) {
        int b = task >> 10, i = task & 1023;
        int w = node_w(i), ns = node_start(i);
        size_t ebase = (size_t)b*Ee + ns;
        int srow0 = (b << 10) + (i - w);
        int ntask = task + NSTREAM;
        bool hasn = ntask < NTASK;
        float* sredW = sredB + par*512;
        ull*   swrW  = swrB + par*256;
        float* sndC  = sndB + par*64;
        float* sndN  = sndB + (par^1)*64;

        // ---- GEMM1: Q = A @ Wcat (R5 layout: warp rows, col-pair W) ----
        ull acc[4][6];
        #pragma unroll
        for (int q = 0; q < 4; q++)
            #pragma unroll
            for (int c2 = 0; c2 < 6; c2++) acc[q][c2] = 0ull;
        #pragma unroll 8
        for (int j = 0; j < 64; j++) {
            ull a2[4];
            #pragma unroll
            for (int q = 0; q < 4; q++) a2[q] = *(const ull*)&curAT[j*66 + r0t + 2*q];
            #pragma unroll
            for (int g = 0; g < 3; g++) {
                float2 wp = *(const float2*)&sW1[j*192 + 64*g + 2*tx];
                ull w20 = bcast2(wp.x);
                ull w21 = bcast2(wp.y);
                #pragma unroll
                for (int q = 0; q < 4; q++) {
                    fma2(acc[q][2*g+0], a2[q], w20);
                    fma2(acc[q][2*g+1], a2[q], w21);
                }
            }
        }

        // ---- per-row node projections (float2 over col pair) ----
        int c0 = 2*tx;
        float2 pnd, pfe[8], pfn[8];
        {
            size_t pb = (size_t)task*192;
            pnd = *(const float2*)&g_P[pb + 128 + c0];
            #pragma unroll
            for (int ri = 0; ri < 8; ri++) {
                size_t sr = (size_t)(srow0 + r0t + ri)*192;
                pfe[ri] = *(const float2*)&g_P[sr + c0];
                pfn[ri] = *(const float2*)&g_P[sr + 64 + c0];
            }
        }
        float2 be2v = *(const float2*)&sbe[c0];
        float2 bn2v = *(const float2*)&sbn[c0];

        // ---- epilogue: ReLU; pair_e -> sPeT (warp-local rows); pair_n partials ----
        float np0 = 0.f, np1 = 0.f;
        #pragma unroll
        for (int q = 0; q < 4; q++) {
            int rA = 2*q, rB = 2*q + 1;
            int gA = (r0t + rA) < w, gB = (r0t + rB) < w;
            float2 e0 = unpk(acc[q][0]);
            float2 e1 = unpk(acc[q][1]);
            float2 n0 = unpk(acc[q][2]);
            float2 n1 = unpk(acc[q][3]);
            float p0A = e0.x + pfe[rA].x + be2v.x;
            float p0B = e0.y + pfe[rB].x + be2v.x;
            p0A = (gA && p0A > 0.f) ? p0A : 0.f;
            p0B = (gB && p0B > 0.f) ? p0B : 0.f;
            *(ull*)&sPeT[(c0+0)*66 + r0t + rA] = pk(p0A, p0B);
            float p1A = e1.x + pfe[rA].y + be2v.y;
            float p1B = e1.y + pfe[rB].y + be2v.y;
            p1A = (gA && p1A > 0.f) ? p1A : 0.f;
            p1B = (gB && p1B > 0.f) ? p1B : 0.f;
            *(ull*)&sPeT[(c0+1)*66 + r0t + rA] = pk(p1A, p1B);
            float q0A = n0.x + pfn[rA].x + pnd.x + bn2v.x;
            float q0B = n0.y + pfn[rB].x + pnd.x + bn2v.x;
            if (gA && q0A > 0.f) np0 += q0A;
            if (gB && q0B > 0.f) np0 += q0B;
            float q1A = n1.x + pfn[rA].y + pnd.y + bn2v.y;
            float q1B = n1.y + pfn[rB].y + pnd.y + bn2v.y;
            if (gA && q1A > 0.f) np1 += q1A;
            if (gB && q1B > 0.f) np1 += q1B;
        }
        *(ull*)&sredW[ty*64 + c0] = pk(np0, np1);

        // ---- prefetch next tile (own-warp rows) + next snode ----
        float4 pf4[4];
        if (hasn) {
            int nb = ntask >> 10, ni = ntask & 1023;
            size_t nebase = (size_t)nb*Ee + node_start(ni);
            const float4* nsrc = (const float4*)(edges + nebase*64);
            #pragma unroll
            for (int k = 0; k < 4; k++) {
                int idx = tx + 32*k;
                pf4[k] = __ldg(nsrc + (r0t + (idx >> 4))*16 + (idx & 15));
            }
            if (gtid < 16) {
                float4 v = __ldg((const float4*)(nodes + (size_t)ntask*64) + gtid);
                *(float4*)&sndN[4*gtid] = v;
            }
        }
        __syncwarp();                        // sPeT rows are warp-local

        // ---- GEMM2: R = pair_e @ W_mean (own sPeT rows) ----
        ull acc20[4], acc21[4];
        #pragma unroll
        for (int p = 0; p < 4; p++) { acc20[p] = 0ull; acc21[p] = 0ull; }
        #pragma unroll 8
        for (int j = 0; j < 64; j++) {
            ull a2[4];
            #pragma unroll
            for (int q = 0; q < 4; q++) a2[q] = *(const ull*)&sPeT[j*66 + r0t + 2*q];
            float2 wp = *(const float2*)&sW2[j*64 + c0];
            ull w20 = bcast2(wp.x);
            ull w21 = bcast2(wp.y);
            #pragma unroll
            for (int q = 0; q < 4; q++) {
                fma2(acc20[q], a2[q], w20);
                fma2(acc21[q], a2[q], w21);
            }
        }

        // ---- exclusive row-prefix (in-register) + warp totals ----
        float s0[8], s1[8];
        #pragma unroll
        for (int q = 0; q < 4; q++) {
            float2 v0 = unpk(acc20[q]);
            float2 v1 = unpk(acc21[q]);
            s0[2*q] = v0.x; s0[2*q+1] = v0.y;
            s1[2*q] = v1.x; s1[2*q+1] = v1.y;
        }
        float ex0[8], ex1[8], run0 = 0.f, run1 = 0.f;
        #pragma unroll
        for (int ri = 0; ri < 8; ri++) {
            ex0[ri] = run0; run0 += s0[ri];
            ex1[ri] = run1; run1 += s1[ri];
        }
        swrW[ty*32 + tx] = pk(run0, run1);

        // ---- store prefetched tile into alternate buffer (own rows) ----
        if (hasn) {
            #pragma unroll
            for (int k = 0; k < 4; k++) {
                int idx = tx + 32*k;
                int r = r0t + (idx >> 4), j = 4*(idx & 15);
                nxtAT[(j+0)*66 + r] = pf4[k].x; nxtAT[(j+1)*66 + r] = pf4[k].y;
                nxtAT[(j+2)*66 + r] = pf4[k].z; nxtAT[(j+3)*66 + r] = pf4[k].w;
            }
        }

        gbar(bar);                           // single group barrier: sred/swred visible

        // ---- warp-carry (predicated, unrolled) ----
        float cc0 = 0.f, cc1 = 0.f;
        #pragma unroll
        for (int t = 0; t < 7; t++) {
            if (t < ty) {
                float2 v = unpk(swrW[t*32 + tx]);
                cc0 += v.x; cc1 += v.y;
            }
        }

        // ---- out_edges: mean-scale + Q3 + bias, ReLU, float2 store ----
        {
            float2 bo2v = *(const float2*)&sbo[c0];
            #pragma unroll
            for (int q = 0; q < 4; q++) {
                float2 t0 = unpk(acc[q][4]);
                float2 t1 = unpk(acc[q][5]);
                #pragma unroll
                for (int h = 0; h < 2; h++) {
                    int ri = 2*q + h;
                    int r  = r0t + ri;
                    if (r < w) {
                        float rc = srcp[r];
                        size_t orow = (ebase + r)*64;
                        float vx = (ex0[ri] + cc0)*rc + (h ? t0.y : t0.x) + bo2v.x;
                        float vy = (ex1[ri] + cc1)*rc + (h ? t1.y : t1.x) + bo2v.y;
                        float2 o; o.x = fmaxf(vx, 0.f); o.y = fmaxf(vy, 0.f);
                        *(float2*)&out_edges[orow + c0] = o;
                    }
                }
            }
        }

        // ---- agg + fused out_nodes (warps 0-1 only; others run ahead) ----
        if (gtid < 64) {
            int c = gtid;
            float a = 0.f;
            #pragma unroll
            for (int t = 0; t < 8; t++) a += sredW[t*64 + c];
            a *= (1.0f / (float)(w > 0 ? w : 1));
            sagg[c] = a;
            mbar64(mb);
            float accn = sbo[c];
            #pragma unroll 8
            for (int j = 0; j < 64; j++) accn += sagg[j] * sW3[j*64 + c];
            #pragma unroll 8
            for (int j = 0; j < 64; j++) accn += sndC[j] * sW3[(64+j)*64 + c];
            out_nodes[(size_t)task*64 + c] = fmaxf(accn, 0.f);
        }

        float* t = curAT; curAT = nxtAT; nxtAT = t;
    }
}

// ---------------- launch ----------------
extern "C" void kernel_launch(void* const* d_in, const int* in_sizes, int n_in,
                              void* d_out, int out_size) {
    const float* input_nodes = (const float*)d_in[0];
    const float* input_edges = (const float*)d_in[1];
    const float* Wn1 = (const float*)d_in[2];
    const float* bn1 = (const float*)d_in[3];
    const float* Wn2 = (const float*)d_in[4];
    const float* bn2 = (const float*)d_in[5];
    const float* We1 = (const float*)d_in[6];
    const float* be1 = (const float*)d_in[7];
    const float* We2 = (const float*)d_in[8];
    const float* be2 = (const float*)d_in[9];
    const float* W_nodes    = (const float*)d_in[10];
    const float* W_edges    = (const float*)d_in[11];
    const float* bias_edges = (const float*)d_in[12];

    float* out       = (float*)d_out;
    float* out_nodes = out;
    float* out_edges = out + (size_t)Bq*Nn*64;

    cudaFuncSetAttribute(k_fusededge, cudaFuncAttributeMaxDynamicSharedMemorySize, SMEM_BYTES);

    k_fuse<<<(128*64 + 192*64 + 128 + 255)/256, 256>>>(We1, We2, be1, be2, Wn1, bn1, Wn2, bn2);
    k_cat<<<(64*192 + 255)/256, 256>>>(W_edges);
    k_nodeproj<<<128, 256>>>(input_nodes);
    k_fusededge<<<GRID, 512, SMEM_BYTES>>>(input_edges, input_nodes, W_edges, W_nodes,
                                           bias_edges, out_edges, out_nodes);
}

// round 9
// speedup vs baseline: 1.4050x; 1.0706x over previous
#include <cuda_runtime.h>

#define Bq 8
#define Nn 1024
#define Mw 64
#define Ee 63456
#define NROWS (Bq*Nn)          /* 8192 node rows */
#define NTASK (Bq*Nn)

#define GRID    152
#define NSTREAM (GRID*2)       /* 304 task streams */

typedef unsigned long long ull;

// ---------------- device scratch ----------------
__device__ float g_Wcat[64*192];        // edge-side:  [We_edge | Wn_edge | W_e_edge]
__device__ float g_WcatP[64*192];       // node-side:  [We_src  | Wn_src  | Wn_dst ]
__device__ float g_be[64];
__device__ float g_bn[64];
__device__ float g_P[NROWS*192];        // node projections [Pes | Pns | Pnd]
__device__ float g_agg[NROWS*64];       // agg_n

__device__ __forceinline__ int node_w(int i)      { return i < Mw ? i : Mw; }
__device__ __forceinline__ int node_start(int i)  { return i <= Mw ? (i*(i-1))/2 : 2016 + (i-Mw)*Mw; }

// ---------------- packed fp32x2 helpers ----------------
__device__ __forceinline__ void fma2(ull &d, ull a, ull b) {
    asm("fma.rn.f32x2 %0, %1, %2, %0;" : "+l"(d) : "l"(a), "l"(b));
}
__device__ __forceinline__ ull bcast2(float x) {
    ull r; asm("mov.b64 %0, {%1, %1};" : "=l"(r) : "f"(x)); return r;
}
__device__ __forceinline__ float2 unpk(ull v) {
    float2 r; asm("mov.b64 {%0, %1}, %2;" : "=f"(r.x), "=f"(r.y) : "l"(v)); return r;
}
__device__ __forceinline__ ull pk(float x, float y) {
    ull r; asm("mov.b64 %0, {%1, %2};" : "=l"(r) : "f"(x), "f"(y)); return r;
}
__device__ __forceinline__ void gbar(int id) {
    asm volatile("bar.sync %0, %1;" :: "r"(id), "r"(256) : "memory");
}

// ---------------- shared layout (floats); tile stride 68 (16B-aligned rows) ----------------
#define STRD     68
#define SZ_AT    (64*STRD)     /* 4352 */
#define OFF_W1   0             /* 12288 */
#define OFF_W2   12288         /* 4096  */
#define OFF_BE   16384
#define OFF_BN   16448
#define OFF_BO   16512
#define OFF_RCP  16576
#define OFF_AT   16640         /* [2 grp][2 buf][4352] = 17408 */
#define OFF_PET  34048         /* [2 grp][4352] = 8704 */
#define OFF_SRED 42752         /* [2 grp][2 par][512] = 2048 */
#define OFF_SWR  44800         /* [2 grp][2 par][256 ull] = 2048 floats */
#define SMEM_FLOATS 46848
#define SMEM_BYTES  (SMEM_FLOATS*4)

// ---------------- K0: build fused weight blocks directly ----------------
__global__ void k_prep(const float* __restrict__ We1, const float* __restrict__ We2,
                       const float* __restrict__ be1, const float* __restrict__ be2,
                       const float* __restrict__ Wn1, const float* __restrict__ bn1,
                       const float* __restrict__ Wn2, const float* __restrict__ bn2,
                       const float* __restrict__ W_edges) {
    int idx = blockIdx.x*blockDim.x + threadIdx.x;
    if (idx < 64*192) {
        int j = idx / 192, c = idx % 192;
        float v;
        if (c < 64) {
            float s = 0.f;
            for (int t = 0; t < 128; t++) s += We1[(64+j)*128+t]*We2[t*64+c];
            v = s;
        } else if (c < 128) {
            int cc = c - 64; float s = 0.f;
            for (int t = 0; t < 128; t++) s += Wn1[(128+j)*128+t]*Wn2[t*64+cc];
            v = s;
        } else {
            v = W_edges[(64+j)*64 + (c-128)];
        }
        g_Wcat[idx] = v;
        return;
    }
    int i2 = idx - 64*192;
    if (i2 >= 0 && i2 < 64*192) {
        int j = i2 / 192, c = i2 % 192;
        float s = 0.f;
        if (c < 64) {
            for (int t = 0; t < 128; t++) s += We1[j*128+t]*We2[t*64+c];
        } else if (c < 128) {
            int cc = c - 64;
            for (int t = 0; t < 128; t++) s += Wn1[j*128+t]*Wn2[t*64+cc];
        } else {
            int cc = c - 128;
            for (int t = 0; t < 128; t++) s += Wn1[(64+j)*128+t]*Wn2[t*64+cc];
        }
        g_WcatP[i2] = s;
        return;
    }
    int i3 = idx - 2*64*192;
    if (i3 >= 0 && i3 < 64) {
        float s = be2[i3];
        for (int t = 0; t < 128; t++) s += be1[t]*We2[t*64+i3];
        g_be[i3] = s;
    } else if (i3 >= 64 && i3 < 128) {
        int c = i3 - 64; float s = bn2[c];
        for (int t = 0; t < 128; t++) s += bn1[t]*Wn2[t*64+c];
        g_bn[c] = s;
    }
}

// ---------------- K1: node projections GEMM (NROWS x 64) @ (64 x 192) ----------------
__global__ void __launch_bounds__(256,2) k_nodeproj(const float* __restrict__ A) {
    __shared__ float sW[64*192];
    __shared__ float sA[64][68];
    for (int idx = threadIdx.x; idx < 64*192; idx += 256) sW[idx] = g_WcatP[idx];
    int tx = threadIdx.x & 31, ty = threadIdx.x >> 5;
    const int NT = NROWS/64;
    for (int tile = blockIdx.x; tile < NT; tile += gridDim.x) {
        __syncthreads();
        const float4* src = (const float4*)(A + (size_t)tile*64*64);
        for (int idx = threadIdx.x; idx < 64*16; idx += 256) {
            int r = idx >> 4, q = idx & 15;
            ((float4*)&sA[r][0])[q] = src[idx];
        }
        __syncthreads();
        float acc[8][6];
        #pragma unroll
        for (int a = 0; a < 8; a++)
            #pragma unroll
            for (int b = 0; b < 6; b++) acc[a][b] = 0.f;
        for (int j = 0; j < 64; j += 4) {
            float4 av[8];
            #pragma unroll
            for (int ri = 0; ri < 8; ri++) av[ri] = *(const float4*)&sA[ty + 8*ri][j];
            #pragma unroll
            for (int jj = 0; jj < 4; jj++) {
                float wv[6];
                #pragma unroll
                for (int ci = 0; ci < 6; ci++) wv[ci] = sW[(j+jj)*192 + tx + 32*ci];
                #pragma unroll
                for (int ri = 0; ri < 8; ri++) {
                    float a = (jj==0) ? av[ri].x : (jj==1) ? av[ri].y : (jj==2) ? av[ri].z : av[ri].w;
                    #pragma unroll
                    for (int ci = 0; ci < 6; ci++) acc[ri][ci] += a * wv[ci];
                }
            }
        }
        float* dst = g_P + (size_t)tile*64*192;
        #pragma unroll
        for (int ri = 0; ri < 8; ri++) {
            int r = ty + 8*ri;
            #pragma unroll
            for (int ci = 0; ci < 6; ci++)
                dst[(size_t)r*192 + tx + 32*ci] = acc[ri][ci];
        }
    }
}

// ---------------- K2: fused pipeline (R5 mapping, 1 gbar/task, LDS.128 A) ----------------
__global__ void __launch_bounds__(512,1) k_fusededge(const float* __restrict__ edges,
                                                     const float* __restrict__ W_edges,
                                                     const float* __restrict__ bias,
                                                     float* __restrict__ out_edges) {
    extern __shared__ float sm[];
    float* sW1  = sm + OFF_W1;
    float* sW2  = sm + OFF_W2;
    float* sbe  = sm + OFF_BE;
    float* sbn  = sm + OFF_BN;
    float* sbo  = sm + OFF_BO;
    float* srcp = sm + OFF_RCP;
    int tid = threadIdx.x;

    for (int idx = tid; idx < 64*192; idx += 512) sW1[idx] = g_Wcat[idx];
    for (int idx = tid; idx < 64*64;  idx += 512) sW2[idx] = W_edges[idx];
    if (tid < 64) {
        sbe[tid] = g_be[tid];
        sbn[tid] = g_bn[tid];
        sbo[tid] = bias[tid];
        srcp[tid] = 1.0f / (float)(tid > 0 ? tid : 1);
    }
    __syncthreads();

    int grp  = tid >> 8;            // warp-group 0/1
    int gtid = tid & 255;
    int tx = gtid & 31, ty = gtid >> 5;
    int bar = grp + 1;
    int r0t = 8*ty;                 // this warp's first row
    int c0 = 2*tx;                  // this thread's first col per 64-segment

    float* sPeT  = sm + OFF_PET  + grp*SZ_AT;
    float* bufA  = sm + OFF_AT + (grp*2+0)*SZ_AT;
    float* bufB  = sm + OFF_AT + (grp*2+1)*SZ_AT;
    float* sredB = sm + OFF_SRED + grp*1024;
    ull*   swrB  = (ull*)(sm + OFF_SWR) + grp*512;

    int task = blockIdx.x*2 + grp;

    // ---- prologue: own-warp rows of first tile ----
    {
        int b = task >> 10, i = task & 1023;
        size_t ebase = (size_t)b*Ee + node_start(i);
        const float4* src = (const float4*)(edges + ebase*64);
        #pragma unroll
        for (int k = 0; k < 4; k++) {
            int idx = tx + 32*k;
            int rl = idx >> 4, q = idx & 15;
            float4 v = __ldg(src + (r0t + rl)*16 + q);
            int j = 4*q, r = r0t + rl;
            bufA[(j+0)*STRD + r] = v.x; bufA[(j+1)*STRD + r] = v.y;
            bufA[(j+2)*STRD + r] = v.z; bufA[(j+3)*STRD + r] = v.w;
        }
    }
    __syncwarp();

    float* curAT = bufA;
    float* nxtAT = bufB;
    int par = 0;

    for (; task < NTASK; task += NSTREAM, par ^= 1) {
        int b = task >> 10, i = task & 1023;
        int w = node_w(i), ns = node_start(i);
        size_t ebase = (size_t)b*Ee + ns;
        int srow0 = (b << 10) + (i - w);
        int ntask = task + NSTREAM;
        bool hasn = ntask < NTASK;
        float* sredW = sredB + par*512;
        ull*   swrW  = swrB + par*256;

        // ---- GEMM1: Q = A @ Wcat (broadcast LDS.128 A, col-pair W) ----
        ull acc[4][6];
        #pragma unroll
        for (int q = 0; q < 4; q++)
            #pragma unroll
            for (int c2 = 0; c2 < 6; c2++) acc[q][c2] = 0ull;
        #pragma unroll 8
        for (int j = 0; j < 64; j++) {
            ulonglong2 aA = *(const ulonglong2*)&curAT[j*STRD + r0t];
            ulonglong2 aB = *(const ulonglong2*)&curAT[j*STRD + r0t + 4];
            ull a2[4] = {aA.x, aA.y, aB.x, aB.y};
            #pragma unroll
            for (int g = 0; g < 3; g++) {
                float2 wp = *(const float2*)&sW1[j*192 + 64*g + c0];
                ull w20 = bcast2(wp.x);
                ull w21 = bcast2(wp.y);
                #pragma unroll
                for (int q = 0; q < 4; q++) {
                    fma2(acc[q][2*g+0], a2[q], w20);
                    fma2(acc[q][2*g+1], a2[q], w21);
                }
            }
        }

        // ---- per-row node projections (float2 over col pair) ----
        float2 pnd, pfe[8], pfn[8];
        {
            size_t pb = (size_t)task*192;
            pnd = *(const float2*)&g_P[pb + 128 + c0];
            #pragma unroll
            for (int ri = 0; ri < 8; ri++) {
                size_t sr = (size_t)(srow0 + r0t + ri)*192;
                pfe[ri] = *(const float2*)&g_P[sr + c0];
                pfn[ri] = *(const float2*)&g_P[sr + 64 + c0];
            }
        }
        float2 be2v = *(const float2*)&sbe[c0];
        float2 bn2v = *(const float2*)&sbn[c0];

        // ---- epilogue: ReLU; pair_e -> sPeT (warp-local rows); pair_n partials ----
        float np0 = 0.f, np1 = 0.f;
        #pragma unroll
        for (int q = 0; q < 4; q++) {
            int rA = 2*q, rB = 2*q + 1;
            int gA = (r0t + rA) < w, gB = (r0t + rB) < w;
            float2 e0 = unpk(acc[q][0]);
            float2 e1 = unpk(acc[q][1]);
            float2 n0 = unpk(acc[q][2]);
            float2 n1 = unpk(acc[q][3]);
            float p0A = e0.x + pfe[rA].x + be2v.x;
            float p0B = e0.y + pfe[rB].x + be2v.x;
            p0A = (gA && p0A > 0.f) ? p0A : 0.f;
            p0B = (gB && p0B > 0.f) ? p0B : 0.f;
            *(ull*)&sPeT[(c0+0)*STRD + r0t + rA] = pk(p0A, p0B);
            float p1A = e1.x + pfe[rA].y + be2v.y;
            float p1B = e1.y + pfe[rB].y + be2v.y;
            p1A = (gA && p1A > 0.f) ? p1A : 0.f;
            p1B = (gB && p1B > 0.f) ? p1B : 0.f;
            *(ull*)&sPeT[(c0+1)*STRD + r0t + rA] = pk(p1A, p1B);
            float q0A = n0.x + pfn[rA].x + pnd.x + bn2v.x;
            float q0B = n0.y + pfn[rB].x + pnd.x + bn2v.x;
            if (gA && q0A > 0.f) np0 += q0A;
            if (gB && q0B > 0.f) np0 += q0B;
            float q1A = n1.x + pfn[rA].y + pnd.y + bn2v.y;
            float q1B = n1.y + pfn[rB].y + pnd.y + bn2v.y;
            if (gA && q1A > 0.f) np1 += q1A;
            if (gB && q1B > 0.f) np1 += q1B;
        }
        *(ull*)&sredW[ty*64 + c0] = pk(np0, np1);

        // ---- prefetch next tile (own-warp rows; LDGs fly under GEMM2) ----
        float4 pf4[4];
        if (hasn) {
            int nb = ntask >> 10, ni = ntask & 1023;
            size_t nebase = (size_t)nb*Ee + node_start(ni);
            const float4* nsrc = (const float4*)(edges + nebase*64);
            #pragma unroll
            for (int k = 0; k < 4; k++) {
                int idx = tx + 32*k;
                pf4[k] = __ldg(nsrc + (r0t + (idx >> 4))*16 + (idx & 15));
            }
        }
        __syncwarp();                        // sPeT rows are warp-local

        // ---- GEMM2: R = pair_e @ W_mean (own sPeT rows) ----
        ull acc20[4], acc21[4];
        #pragma unroll
        for (int p = 0; p < 4; p++) { acc20[p] = 0ull; acc21[p] = 0ull; }
        #pragma unroll 8
        for (int j = 0; j < 64; j++) {
            ulonglong2 aA = *(const ulonglong2*)&sPeT[j*STRD + r0t];
            ulonglong2 aB = *(const ulonglong2*)&sPeT[j*STRD + r0t + 4];
            ull a2[4] = {aA.x, aA.y, aB.x, aB.y};
            float2 wp = *(const float2*)&sW2[j*64 + c0];
            ull w20 = bcast2(wp.x);
            ull w21 = bcast2(wp.y);
            #pragma unroll
            for (int q = 0; q < 4; q++) {
                fma2(acc20[q], a2[q], w20);
                fma2(acc21[q], a2[q], w21);
            }
        }

        // ---- exclusive row-prefix (in-register) + warp totals ----
        float s0[8], s1[8];
        #pragma unroll
        for (int q = 0; q < 4; q++) {
            float2 v0 = unpk(acc20[q]);
            float2 v1 = unpk(acc21[q]);
            s0[2*q] = v0.x; s0[2*q+1] = v0.y;
            s1[2*q] = v1.x; s1[2*q+1] = v1.y;
        }
        float ex0[8], ex1[8], run0 = 0.f, run1 = 0.f;
        #pragma unroll
        for (int ri = 0; ri < 8; ri++) {
            ex0[ri] = run0; run0 += s0[ri];
            ex1[ri] = run1; run1 += s1[ri];
        }
        swrW[ty*32 + tx] = pk(run0, run1);

        // ---- store prefetched tile into alternate buffer (own rows) ----
        if (hasn) {
            #pragma unroll
            for (int k = 0; k < 4; k++) {
                int idx = tx + 32*k;
                int r = r0t + (idx >> 4), j = 4*(idx & 15);
                nxtAT[(j+0)*STRD + r] = pf4[k].x; nxtAT[(j+1)*STRD + r] = pf4[k].y;
                nxtAT[(j+2)*STRD + r] = pf4[k].z; nxtAT[(j+3)*STRD + r] = pf4[k].w;
            }
        }

        gbar(bar);                           // single group barrier: sred/swr visible

        // ---- warp-carry (predicated, unrolled) ----
        float cc0 = 0.f, cc1 = 0.f;
        #pragma unroll
        for (int t = 0; t < 7; t++) {
            if (t < ty) {
                float2 v = unpk(swrW[t*32 + tx]);
                cc0 += v.x; cc1 += v.y;
            }
        }

        // ---- out_edges: mean-scale + Q3 + bias, ReLU, float2 store ----
        {
            float2 bo2v = *(const float2*)&sbo[c0];
            #pragma unroll
            for (int q = 0; q < 4; q++) {
                float2 t0 = unpk(acc[q][4]);
                float2 t1 = unpk(acc[q][5]);
                #pragma unroll
                for (int h = 0; h < 2; h++) {
                    int ri = 2*q + h;
                    int r  = r0t + ri;
                    if (r < w) {
                        float rc = srcp[r];
                        size_t orow = (ebase + r)*64;
                        float vx = (ex0[ri] + cc0)*rc + (h ? t0.y : t0.x) + bo2v.x;
                        float vy = (ex1[ri] + cc1)*rc + (h ? t1.y : t1.x) + bo2v.y;
                        float2 o; o.x = fmaxf(vx, 0.f); o.y = fmaxf(vy, 0.f);
                        *(float2*)&out_edges[orow + c0] = o;
                    }
                }
            }
        }

        // ---- agg_n write (64 threads; no extra barrier needed) ----
        if (gtid < 64) {
            int c = gtid;
            float a = 0.f;
            #pragma unroll
            for (int t = 0; t < 8; t++) a += sredW[t*64 + c];
            g_agg[(size_t)task*64 + c] = a * (1.0f / (float)(w > 0 ? w : 1));
        }

        float* t = curAT; curAT = nxtAT; nxtAT = t;
    }
}

// ---------------- K3: out_nodes (NROWS x 128) @ (128 x 64) ----------------
__global__ void __launch_bounds__(256,2) k_outnodes(float* __restrict__ out,
                                                    const float* __restrict__ nodes,
                                                    const float* __restrict__ W_nodes,
                                                    const float* __restrict__ bias) {
    __shared__ float sW[128*64];
    __shared__ float sA[64][132];
    __shared__ float sb[64];
    for (int idx = threadIdx.x; idx < 128*64; idx += 256) sW[idx] = W_nodes[idx];
    if (threadIdx.x < 64) sb[threadIdx.x] = bias[threadIdx.x];
    int tx = threadIdx.x & 31, ty = threadIdx.x >> 5;
    int tile = blockIdx.x;
    {
        const float4* sa = (const float4*)(g_agg + (size_t)tile*64*64);
        const float4* sn = (const float4*)(nodes + (size_t)tile*64*64);
        for (int idx = threadIdx.x; idx < 64*16; idx += 256) {
            int r = idx >> 4, q = idx & 15;
            ((float4*)&sA[r][0])[q]  = sa[idx];
            ((float4*)&sA[r][64])[q] = sn[idx];
        }
    }
    __syncthreads();
    float acc[8][2];
    #pragma unroll
    for (int a = 0; a < 8; a++) { acc[a][0] = 0.f; acc[a][1] = 0.f; }
    for (int j = 0; j < 128; j += 4) {
        float4 av[8];
        #pragma unroll
        for (int ri = 0; ri < 8; ri++) av[ri] = *(const float4*)&sA[ty + 8*ri][j];
        #pragma unroll
        for (int jj = 0; jj < 4; jj++) {
            float w0 = sW[(j+jj)*64 + tx];
            float w1 = sW[(j+jj)*64 + tx + 32];
            #pragma unroll
            for (int ri = 0; ri < 8; ri++) {
                float a = (jj==0) ? av[ri].x : (jj==1) ? av[ri].y : (jj==2) ? av[ri].z : av[ri].w;
                acc[ri][0] += a * w0;
                acc[ri][1] += a * w1;
            }
        }
    }
    #pragma unroll
    for (int ri = 0; ri < 8; ri++) {
        size_t row = (size_t)tile*64 + ty + 8*ri;
        float v0 = acc[ri][0] + sb[tx];
        float v1 = acc[ri][1] + sb[tx+32];
        out[row*64 + tx]      = v0 > 0.f ? v0 : 0.f;
        out[row*64 + tx + 32] = v1 > 0.f ? v1 : 0.f;
    }
}

// ---------------- launch ----------------
extern "C" void kernel_launch(void* const* d_in, const int* in_sizes, int n_in,
                              void* d_out, int out_size) {
    const float* input_nodes = (const float*)d_in[0];
    const float* input_edges = (const float*)d_in[1];
    const float* Wn1 = (const float*)d_in[2];
    const float* bn1 = (const float*)d_in[3];
    const float* Wn2 = (const float*)d_in[4];
    const float* bn2 = (const float*)d_in[5];
    const float* We1 = (const float*)d_in[6];
    const float* be1 = (const float*)d_in[7];
    const float* We2 = (const float*)d_in[8];
    const float* be2 = (const float*)d_in[9];
    const float* W_nodes    = (const float*)d_in[10];
    const float* W_edges    = (const float*)d_in[11];
    const float* bias_edges = (const float*)d_in[12];

    float* out       = (float*)d_out;
    float* out_nodes = out;
    float* out_edges = out + (size_t)Bq*Nn*64;

    cudaFuncSetAttribute(k_fusededge, cudaFuncAttributeMaxDynamicSharedMemorySize, SMEM_BYTES);

    k_prep<<<(2*64*192 + 128 + 255)/256, 256>>>(We1, We2, be1, be2, Wn1, bn1, Wn2, bn2, W_edges);
    k_nodeproj<<<128, 256>>>(input_nodes);
    k_fusededge<<<GRID, 512, SMEM_BYTES>>>(input_edges, W_edges, bias_edges, out_edges);
    k_outnodes<<<128, 256>>>(out_nodes, input_nodes, W_nodes, bias_edges);
}

// round 10
// speedup vs baseline: 1.4114x; 1.0045x over previous
#include <cuda_runtime.h>

#define Bq 8
#define Nn 1024
#define Mw 64
#define Ee 63456
#define NROWS (Bq*Nn)          /* 8192 node rows */
#define NTASK (Bq*Nn)

#define GRID    152
#define NSTREAM (GRID*2)       /* 304 task streams */

typedef unsigned long long ull;

// ---------------- device scratch ----------------
__device__ float g_Wcat[64*192];        // edge-side:  [We_edge | Wn_edge | W_e_edge]
__device__ float g_WcatP[64*192];       // node-side:  [We_src  | Wn_src  | Wn_dst ]
__device__ float g_be[64];
__device__ float g_bn[64];
__device__ float g_P[NROWS*192];        // node projections [Pes | Pns | Pnd]
__device__ float g_agg[NROWS*64];       // agg_n

__device__ __forceinline__ int node_w(int i)      { return i < Mw ? i : Mw; }
__device__ __forceinline__ int node_start(int i)  { return i <= Mw ? (i*(i-1))/2 : 2016 + (i-Mw)*Mw; }

// ---------------- packed fp32x2 helpers ----------------
__device__ __forceinline__ void fma2(ull &d, ull a, ull b) {
    asm("fma.rn.f32x2 %0, %1, %2, %0;" : "+l"(d) : "l"(a), "l"(b));
}
__device__ __forceinline__ ull bcast2(float x) {
    ull r; asm("mov.b64 %0, {%1, %1};" : "=l"(r) : "f"(x)); return r;
}
__device__ __forceinline__ float2 unpk(ull v) {
    float2 r; asm("mov.b64 {%0, %1}, %2;" : "=f"(r.x), "=f"(r.y) : "l"(v)); return r;
}
__device__ __forceinline__ ull pk(float x, float y) {
    ull r; asm("mov.b64 %0, {%1, %2};" : "=l"(r) : "f"(x), "f"(y)); return r;
}
__device__ __forceinline__ void gbar(int id) {
    asm volatile("bar.sync %0, %1;" :: "r"(id), "r"(256) : "memory");
}
// pinned-placement vector load (volatile: ptxas cannot sink it)
__device__ __forceinline__ float2 ldg2v(const float* p) {
    float2 v;
    asm volatile("ld.global.nc.v2.f32 {%0, %1}, [%2];" : "=f"(v.x), "=f"(v.y) : "l"(p));
    return v;
}

// ---------------- shared layout (floats); tile stride 68 (16B-aligned rows) ----------------
#define STRD     68
#define SZ_AT    (64*STRD)     /* 4352 */
#define OFF_W1   0             /* 12288 */
#define OFF_W2   12288         /* 4096  */
#define OFF_BE   16384
#define OFF_BN   16448
#define OFF_BO   16512
#define OFF_RCP  16576
#define OFF_AT   16640         /* [2 grp][2 buf][4352] = 17408 */
#define OFF_PET  34048         /* [2 grp][4352] = 8704 */
#define OFF_SRED 42752         /* [2 grp][2 par][512] = 2048 */
#define OFF_SWR  44800         /* [2 grp][2 par][256 ull] = 2048 floats */
#define SMEM_FLOATS 46848
#define SMEM_BYTES  (SMEM_FLOATS*4)

// ---------------- K0: build fused weight blocks directly ----------------
__global__ void k_prep(const float* __restrict__ We1, const float* __restrict__ We2,
                       const float* __restrict__ be1, const float* __restrict__ be2,
                       const float* __restrict__ Wn1, const float* __restrict__ bn1,
                       const float* __restrict__ Wn2, const float* __restrict__ bn2,
                       const float* __restrict__ W_edges) {
    int idx = blockIdx.x*blockDim.x + threadIdx.x;
    if (idx < 64*192) {
        int j = idx / 192, c = idx % 192;
        float v;
        if (c < 64) {
            float s = 0.f;
            for (int t = 0; t < 128; t++) s += We1[(64+j)*128+t]*We2[t*64+c];
            v = s;
        } else if (c < 128) {
            int cc = c - 64; float s = 0.f;
            for (int t = 0; t < 128; t++) s += Wn1[(128+j)*128+t]*Wn2[t*64+cc];
            v = s;
        } else {
            v = W_edges[(64+j)*64 + (c-128)];
        }
        g_Wcat[idx] = v;
        return;
    }
    int i2 = idx - 64*192;
    if (i2 >= 0 && i2 < 64*192) {
        int j = i2 / 192, c = i2 % 192;
        float s = 0.f;
        if (c < 64) {
            for (int t = 0; t < 128; t++) s += We1[j*128+t]*We2[t*64+c];
        } else if (c < 128) {
            int cc = c - 64;
            for (int t = 0; t < 128; t++) s += Wn1[j*128+t]*Wn2[t*64+cc];
        } else {
            int cc = c - 128;
            for (int t = 0; t < 128; t++) s += Wn1[(64+j)*128+t]*Wn2[t*64+cc];
        }
        g_WcatP[i2] = s;
        return;
    }
    int i3 = idx - 2*64*192;
    if (i3 >= 0 && i3 < 64) {
        float s = be2[i3];
        for (int t = 0; t < 128; t++) s += be1[t]*We2[t*64+i3];
        g_be[i3] = s;
    } else if (i3 >= 64 && i3 < 128) {
        int c = i3 - 64; float s = bn2[c];
        for (int t = 0; t < 128; t++) s += bn1[t]*Wn2[t*64+c];
        g_bn[c] = s;
    }
}

// ---------------- K1: node projections GEMM; 256 blocks x 32-row tiles ----------------
__global__ void __launch_bounds__(256,2) k_nodeproj(const float* __restrict__ A) {
    __shared__ float sW[64*192];
    __shared__ float sA[32][68];
    for (int idx = threadIdx.x; idx < 64*192; idx += 256) sW[idx] = g_WcatP[idx];
    int tx = threadIdx.x & 31, ty = threadIdx.x >> 5;
    int tile = blockIdx.x;                 // 256 tiles of 32 rows
    {
        const float4* src = (const float4*)(A + (size_t)tile*32*64);
        for (int idx = threadIdx.x; idx < 32*16; idx += 256) {
            int r = idx >> 4, q = idx & 15;
            ((float4*)&sA[r][0])[q] = src[idx];
        }
    }
    __syncthreads();
    float acc[4][6];
    #pragma unroll
    for (int a = 0; a < 4; a++)
        #pragma unroll
        for (int b = 0; b < 6; b++) acc[a][b] = 0.f;
    for (int j = 0; j < 64; j += 4) {
        float4 av[4];
        #pragma unroll
        for (int ri = 0; ri < 4; ri++) av[ri] = *(const float4*)&sA[ty*4 + ri][j];
        #pragma unroll
        for (int jj = 0; jj < 4; jj++) {
            float wv[6];
            #pragma unroll
            for (int ci = 0; ci < 6; ci++) wv[ci] = sW[(j+jj)*192 + tx + 32*ci];
            #pragma unroll
            for (int ri = 0; ri < 4; ri++) {
                float a = (jj==0) ? av[ri].x : (jj==1) ? av[ri].y : (jj==2) ? av[ri].z : av[ri].w;
                #pragma unroll
                for (int ci = 0; ci < 6; ci++) acc[ri][ci] += a * wv[ci];
            }
        }
    }
    float* dst = g_P + (size_t)tile*32*192;
    #pragma unroll
    for (int ri = 0; ri < 4; ri++) {
        int r = ty*4 + ri;
        #pragma unroll
        for (int ci = 0; ci < 6; ci++)
            dst[(size_t)r*192 + tx + 32*ci] = acc[ri][ci];
    }
}

// ---------------- K2: fused pipeline (R9 structure + split-loop g_P prefetch) ----------------
__global__ void __launch_bounds__(512,1) k_fusededge(const float* __restrict__ edges,
                                                     const float* __restrict__ W_edges,
                                                     const float* __restrict__ bias,
                                                     float* __restrict__ out_edges) {
    extern __shared__ float sm[];
    float* sW1  = sm + OFF_W1;
    float* sW2  = sm + OFF_W2;
    float* sbe  = sm + OFF_BE;
    float* sbn  = sm + OFF_BN;
    float* sbo  = sm + OFF_BO;
    float* srcp = sm + OFF_RCP;
    int tid = threadIdx.x;

    for (int idx = tid; idx < 64*192; idx += 512) sW1[idx] = g_Wcat[idx];
    for (int idx = tid; idx < 64*64;  idx += 512) sW2[idx] = W_edges[idx];
    if (tid < 64) {
        sbe[tid] = g_be[tid];
        sbn[tid] = g_bn[tid];
        sbo[tid] = bias[tid];
        srcp[tid] = 1.0f / (float)(tid > 0 ? tid : 1);
    }
    __syncthreads();

    int grp  = tid >> 8;            // warp-group 0/1
    int gtid = tid & 255;
    int tx = gtid & 31, ty = gtid >> 5;
    int bar = grp + 1;
    int r0t = 8*ty;                 // this warp's first row
    int c0 = 2*tx;                  // this thread's first col per 64-segment

    float* sPeT  = sm + OFF_PET  + grp*SZ_AT;
    float* bufA  = sm + OFF_AT + (grp*2+0)*SZ_AT;
    float* bufB  = sm + OFF_AT + (grp*2+1)*SZ_AT;
    float* sredB = sm + OFF_SRED + grp*1024;
    ull*   swrB  = (ull*)(sm + OFF_SWR) + grp*512;

    int task = blockIdx.x*2 + grp;

    // ---- prologue: own-warp rows of first tile ----
    {
        int b = task >> 10, i = task & 1023;
        size_t ebase = (size_t)b*Ee + node_start(i);
        const float4* src = (const float4*)(edges + ebase*64);
        #pragma unroll
        for (int k = 0; k < 4; k++) {
            int idx = tx + 32*k;
            int rl = idx >> 4, q = idx & 15;
            float4 v = __ldg(src + (r0t + rl)*16 + q);
            int j = 4*q, r = r0t + rl;
            bufA[(j+0)*STRD + r] = v.x; bufA[(j+1)*STRD + r] = v.y;
            bufA[(j+2)*STRD + r] = v.z; bufA[(j+3)*STRD + r] = v.w;
        }
    }
    __syncwarp();

    float* curAT = bufA;
    float* nxtAT = bufB;
    int par = 0;

    for (; task < NTASK; task += NSTREAM, par ^= 1) {
        int b = task >> 10, i = task & 1023;
        int w = node_w(i), ns = node_start(i);
        size_t ebase = (size_t)b*Ee + ns;
        int srow0 = (b << 10) + (i - w);
        int ntask = task + NSTREAM;
        bool hasn = ntask < NTASK;
        float* sredW = sredB + par*512;
        ull*   swrW  = swrB + par*256;

        // ---- GEMM1 part A: j = 0..47 ----
        ull acc[4][6];
        #pragma unroll
        for (int q = 0; q < 4; q++)
            #pragma unroll
            for (int c2 = 0; c2 < 6; c2++) acc[q][c2] = 0ull;
        #pragma unroll 8
        for (int j = 0; j < 48; j++) {
            ulonglong2 aA = *(const ulonglong2*)&curAT[j*STRD + r0t];
            ulonglong2 aB = *(const ulonglong2*)&curAT[j*STRD + r0t + 4];
            ull a2[4] = {aA.x, aA.y, aB.x, aB.y};
            #pragma unroll
            for (int g = 0; g < 3; g++) {
                float2 wp = *(const float2*)&sW1[j*192 + 64*g + c0];
                ull w20 = bcast2(wp.x);
                ull w21 = bcast2(wp.y);
                #pragma unroll
                for (int q = 0; q < 4; q++) {
                    fma2(acc[q][2*g+0], a2[q], w20);
                    fma2(acc[q][2*g+1], a2[q], w21);
                }
            }
        }

        // ---- issue g_P loads NOW (volatile: covered by remaining 16 j-iters) ----
        float2 pnd, pfe[8], pfn[8];
        {
            size_t pb = (size_t)task*192;
            pnd = ldg2v(&g_P[pb + 128 + c0]);
            #pragma unroll
            for (int ri = 0; ri < 8; ri++) {
                size_t sr = (size_t)(srow0 + r0t + ri)*192;
                pfe[ri] = ldg2v(&g_P[sr + c0]);
                pfn[ri] = ldg2v(&g_P[sr + 64 + c0]);
            }
        }

        // ---- GEMM1 part B: j = 48..63 ----
        #pragma unroll 8
        for (int j = 48; j < 64; j++) {
            ulonglong2 aA = *(const ulonglong2*)&curAT[j*STRD + r0t];
            ulonglong2 aB = *(const ulonglong2*)&curAT[j*STRD + r0t + 4];
            ull a2[4] = {aA.x, aA.y, aB.x, aB.y};
            #pragma unroll
            for (int g = 0; g < 3; g++) {
                float2 wp = *(const float2*)&sW1[j*192 + 64*g + c0];
                ull w20 = bcast2(wp.x);
                ull w21 = bcast2(wp.y);
                #pragma unroll
                for (int q = 0; q < 4; q++) {
                    fma2(acc[q][2*g+0], a2[q], w20);
                    fma2(acc[q][2*g+1], a2[q], w21);
                }
            }
        }

        float2 be2v = *(const float2*)&sbe[c0];
        float2 bn2v = *(const float2*)&sbn[c0];

        // ---- epilogue: ReLU; pair_e -> sPeT (warp-local rows); pair_n partials ----
        float np0 = 0.f, np1 = 0.f;
        #pragma unroll
        for (int q = 0; q < 4; q++) {
            int rA = 2*q, rB = 2*q + 1;
            int gA = (r0t + rA) < w, gB = (r0t + rB) < w;
            float2 e0 = unpk(acc[q][0]);
            float2 e1 = unpk(acc[q][1]);
            float2 n0 = unpk(acc[q][2]);
            float2 n1 = unpk(acc[q][3]);
            float p0A = e0.x + pfe[rA].x + be2v.x;
            float p0B = e0.y + pfe[rB].x + be2v.x;
            p0A = (gA && p0A > 0.f) ? p0A : 0.f;
            p0B = (gB && p0B > 0.f) ? p0B : 0.f;
            *(ull*)&sPeT[(c0+0)*STRD + r0t + rA] = pk(p0A, p0B);
            float p1A = e1.x + pfe[rA].y + be2v.y;
            float p1B = e1.y + pfe[rB].y + be2v.y;
            p1A = (gA && p1A > 0.f) ? p1A : 0.f;
            p1B = (gB && p1B > 0.f) ? p1B : 0.f;
            *(ull*)&sPeT[(c0+1)*STRD + r0t + rA] = pk(p1A, p1B);
            float q0A = n0.x + pfn[rA].x + pnd.x + bn2v.x;
            float q0B = n0.y + pfn[rB].x + pnd.x + bn2v.x;
            if (gA && q0A > 0.f) np0 += q0A;
            if (gB && q0B > 0.f) np0 += q0B;
            float q1A = n1.x + pfn[rA].y + pnd.y + bn2v.y;
            float q1B = n1.y + pfn[rB].y + pnd.y + bn2v.y;
            if (gA && q1A > 0.f) np1 += q1A;
            if (gB && q1B > 0.f) np1 += q1B;
        }
        *(ull*)&sredW[ty*64 + c0] = pk(np0, np1);

        // ---- prefetch next tile (own-warp rows; LDGs fly under GEMM2) ----
        float4 pf4[4];
        if (hasn) {
            int nb = ntask >> 10, ni = ntask & 1023;
            size_t nebase = (size_t)nb*Ee + node_start(ni);
            const float4* nsrc = (const float4*)(edges + nebase*64);
            #pragma unroll
            for (int k = 0; k < 4; k++) {
                int idx = tx + 32*k;
                pf4[k] = __ldg(nsrc + (r0t + (idx >> 4))*16 + (idx & 15));
            }
        }
        __syncwarp();                        // sPeT rows are warp-local

        // ---- GEMM2: R = pair_e @ W_mean (own sPeT rows) ----
        ull acc20[4], acc21[4];
        #pragma unroll
        for (int p = 0; p < 4; p++) { acc20[p] = 0ull; acc21[p] = 0ull; }
        #pragma unroll 8
        for (int j = 0; j < 64; j++) {
            ulonglong2 aA = *(const ulonglong2*)&sPeT[j*STRD + r0t];
            ulonglong2 aB = *(const ulonglong2*)&sPeT[j*STRD + r0t + 4];
            ull a2[4] = {aA.x, aA.y, aB.x, aB.y};
            float2 wp = *(const float2*)&sW2[j*64 + c0];
            ull w20 = bcast2(wp.x);
            ull w21 = bcast2(wp.y);
            #pragma unroll
            for (int q = 0; q < 4; q++) {
                fma2(acc20[q], a2[q], w20);
                fma2(acc21[q], a2[q], w21);
            }
        }

        // ---- exclusive row-prefix (in-register) + warp totals ----
        float s0[8], s1[8];
        #pragma unroll
        for (int q = 0; q < 4; q++) {
            float2 v0 = unpk(acc20[q]);
            float2 v1 = unpk(acc21[q]);
            s0[2*q] = v0.x; s0[2*q+1] = v0.y;
            s1[2*q] = v1.x; s1[2*q+1] = v1.y;
        }
        float ex0[8], ex1[8], run0 = 0.f, run1 = 0.f;
        #pragma unroll
        for (int ri = 0; ri < 8; ri++) {
            ex0[ri] = run0; run0 += s0[ri];
            ex1[ri] = run1; run1 += s1[ri];
        }
        swrW[ty*32 + tx] = pk(run0, run1);

        // ---- store prefetched tile into alternate buffer (own rows) ----
        if (hasn) {
            #pragma unroll
            for (int k = 0; k < 4; k++) {
                int idx = tx + 32*k;
                int r = r0t + (idx >> 4), j = 4*(idx & 15);
                nxtAT[(j+0)*STRD + r] = pf4[k].x; nxtAT[(j+1)*STRD + r] = pf4[k].y;
                nxtAT[(j+2)*STRD + r] = pf4[k].z; nxtAT[(j+3)*STRD + r] = pf4[k].w;
            }
        }

        gbar(bar);                           // single group barrier: sred/swr visible

        // ---- warp-carry (predicated, unrolled) ----
        float cc0 = 0.f, cc1 = 0.f;
        #pragma unroll
        for (int t = 0; t < 7; t++) {
            if (t < ty) {
                float2 v = unpk(swrW[t*32 + tx]);
                cc0 += v.x; cc1 += v.y;
            }
        }

        // ---- out_edges: mean-scale + Q3 + bias, ReLU, float2 store ----
        {
            float2 bo2v = *(const float2*)&sbo[c0];
            #pragma unroll
            for (int q = 0; q < 4; q++) {
                float2 t0 = unpk(acc[q][4]);
                float2 t1 = unpk(acc[q][5]);
                #pragma unroll
                for (int h = 0; h < 2; h++) {
                    int ri = 2*q + h;
                    int r  = r0t + ri;
                    if (r < w) {
                        float rc = srcp[r];
                        size_t orow = (ebase + r)*64;
                        float vx = (ex0[ri] + cc0)*rc + (h ? t0.y : t0.x) + bo2v.x;
                        float vy = (ex1[ri] + cc1)*rc + (h ? t1.y : t1.x) + bo2v.y;
                        float2 o; o.x = fmaxf(vx, 0.f); o.y = fmaxf(vy, 0.f);
                        *(float2*)&out_edges[orow + c0] = o;
                    }
                }
            }
        }

        // ---- agg_n write (64 threads; no extra barrier needed) ----
        if (gtid < 64) {
            int c = gtid;
            float a = 0.f;
            #pragma unroll
            for (int t = 0; t < 8; t++) a += sredW[t*64 + c];
            g_agg[(size_t)task*64 + c] = a * (1.0f / (float)(w > 0 ? w : 1));
        }

        float* t = curAT; curAT = nxtAT; nxtAT = t;
    }
}

// ---------------- K3: out_nodes; 256 blocks x 32-row tiles ----------------
__global__ void __launch_bounds__(256,2) k_outnodes(float* __restrict__ out,
                                                    const float* __restrict__ nodes,
                                                    const float* __restrict__ W_nodes,
                                                    const float* __restrict__ bias) {
    __shared__ float sW[128*64];
    __shared__ float sA[32][132];
    __shared__ float sb[64];
    for (int idx = threadIdx.x; idx < 128*64; idx += 256) sW[idx] = W_nodes[idx];
    if (threadIdx.x < 64) sb[threadIdx.x] = bias[threadIdx.x];
    int tx = threadIdx.x & 31, ty = threadIdx.x >> 5;
    int tile = blockIdx.x;                 // 256 tiles of 32 rows
    {
        const float4* sa = (const float4*)(g_agg + (size_t)tile*32*64);
        const float4* sn = (const float4*)(nodes + (size_t)tile*32*64);
        for (int idx = threadIdx.x; idx < 32*16; idx += 256) {
            int r = idx >> 4, q = idx & 15;
            ((float4*)&sA[r][0])[q]  = sa[idx];
            ((float4*)&sA[r][64])[q] = sn[idx];
        }
    }
    __syncthreads();
    float acc[4][2];
    #pragma unroll
    for (int a = 0; a < 4; a++) { acc[a][0] = 0.f; acc[a][1] = 0.f; }
    for (int j = 0; j < 128; j += 4) {
        float4 av[4];
        #pragma unroll
        for (int ri = 0; ri < 4; ri++) av[ri] = *(const float4*)&sA[ty*4 + ri][j];
        #pragma unroll
        for (int jj = 0; jj < 4; jj++) {
            float w0 = sW[(j+jj)*64 + tx];
            float w1 = sW[(j+jj)*64 + tx + 32];
            #pragma unroll
            for (int ri = 0; ri < 4; ri++) {
                float a = (jj==0) ? av[ri].x : (jj==1) ? av[ri].y : (jj==2) ? av[ri].z : av[ri].w;
                acc[ri][0] += a * w0;
                acc[ri][1] += a * w1;
            }
        }
    }
    #pragma unroll
    for (int ri = 0; ri < 4; ri++) {
        size_t row = (size_t)tile*32 + ty*4 + ri;
        float v0 = acc[ri][0] + sb[tx];
        float v1 = acc[ri][1] + sb[tx+32];
        out[row*64 + tx]      = v0 > 0.f ? v0 : 0.f;
        out[row*64 + tx + 32] = v1 > 0.f ? v1 : 0.f;
    }
}

// ---------------- launch ----------------
extern "C" void kernel_launch(void* const* d_in, const int* in_sizes, int n_in,
                              void* d_out, int out_size) {
    const float* input_nodes = (const float*)d_in[0];
    const float* input_edges = (const float*)d_in[1];
    const float* Wn1 = (const float*)d_in[2];
    const float* bn1 = (const float*)d_in[3];
    const float* Wn2 = (const float*)d_in[4];
    const float* bn2 = (const float*)d_in[5];
    const float* We1 = (const float*)d_in[6];
    const float* be1 = (const float*)d_in[7];
    const float* We2 = (const float*)d_in[8];
    const float* be2 = (const float*)d_in[9];
    const float* W_nodes    = (const float*)d_in[10];
    const float* W_edges    = (const float*)d_in[11];
    const float* bias_edges = (const float*)d_in[12];

    float* out       = (float*)d_out;
    float* out_nodes = out;
    float* out_edges = out + (size_t)Bq*Nn*64;

    cudaFuncSetAttribute(k_fusededge, cudaFuncAttributeMaxDynamicSharedMemorySize, SMEM_BYTES);

    k_prep<<<(2*64*192 + 128 + 255)/256, 256>>>(We1, We2, be1, be2, Wn1, bn1, Wn2, bn2, W_edges);
    k_nodeproj<<<256, 256>>>(input_nodes);
    k_fusededge<<<GRID, 512, SMEM_BYTES>>>(input_edges, W_edges, bias_edges, out_edges);
    k_outnodes<<<256, 256>>>(out_nodes, input_nodes, W_nodes, bias_edges);
}